// round 4
// baseline (speedup 1.0000x reference)
#include <cuda_runtime.h>
#include <cuda_bf16.h>
#include <cstdint>

// Problem constants (fixed by reference setup_inputs)
#define BB 4
#define NN 4096
#define DD 1024
#define HH 16
#define DH 64
#define NCH 32          // chunks along sequence
#define LCH 128         // steps per chunk (NN / NCH)
#define EPSF 1e-6f

// ---------------- scratch (__device__ globals: allocation-free) -------------
__device__ float g_lam[HH];
__device__ float g_c[HH];
__device__ float g_lamL[HH];                       // lam^LCH
__device__ float g_carry[BB * NCH * DD];
__device__ float g_inflow[BB * NCH * DD];
__device__ float g_ynorm[(size_t)BB * NN * DD];    // 64 MB fp32 normalized activations

// ---------------- K0: per-head constants ------------------------------------
__global__ void setup_kernel(const float* __restrict__ q,
                             const float* __restrict__ k,
                             const float* __restrict__ ld) {
    int h = threadIdx.x;
    if (h < HH) {
        float lam = 1.f / (1.f + expf(-ld[h]));   // sigmoid
        float c = 0.f;
        #pragma unroll
        for (int i = 0; i < DH; i++) c += q[h * DH + i] * k[h * DH + i];
        float p = lam;                             // lam^128 via 7 squarings
        #pragma unroll
        for (int it = 0; it < 7; it++) p = p * p;
        g_lam[h] = lam;
        g_c[h] = c;
        g_lamL[h] = p;
    }
}

// ---------------- K1: per-chunk carries --------------------------------------
// grid (NCH, BB), block 1024. Thread d owns channel d of (b, chunk).
__global__ void scan_carry_kernel(const float* __restrict__ x) {
    int d = threadIdx.x;
    int ch = blockIdx.x;
    int b = blockIdx.y;
    int h = d >> 6;
    float lam = g_lam[h], c = g_c[h];
    const float* xp = x + ((size_t)(b * NN) + ch * LCH) * DD + d;
    float y = 0.f;
    #pragma unroll 8
    for (int t = 0; t < LCH; t++) {
        y = lam * y + c * xp[(size_t)t * DD];
    }
    g_carry[(b * NCH + ch) * DD + d] = y;
}

// ---------------- K2: serial combine across 32 chunks ------------------------
// grid BB, block 1024
__global__ void scan_combine_kernel() {
    int d = threadIdx.x;
    int b = blockIdx.x;
    int h = d >> 6;
    float lamL = g_lamL[h];
    float s = 0.f;
    int base = b * NCH * DD + d;
    #pragma unroll
    for (int ch = 0; ch < NCH; ch++) {
        g_inflow[base + ch * DD] = s;
        s = lamL * s + g_carry[base + ch * DD];
    }
}

// ---------------- K3: final scan fused with RMSNorm --------------------------
// grid (NCH, BB), block 1024 (= all D channels of a row). At each timestep the
// whole normalized row lives across the block -> block reduce for RMS.
__global__ void scan_norm_kernel(const float* __restrict__ x,
                                 const float* __restrict__ nw) {
    __shared__ float red[32];
    int d = threadIdx.x;
    int ch = blockIdx.x;
    int b = blockIdx.y;
    int h = d >> 6;
    float lam = g_lam[h], c = g_c[h];
    float w = nw[d];
    float y = g_inflow[(b * NCH + ch) * DD + d];
    size_t rowbase = ((size_t)(b * NN) + ch * LCH) * DD + d;
    const float* xp = x + rowbase;
    float* yp = g_ynorm + rowbase;
    int lane = d & 31, wid = d >> 5;

    for (int t = 0; t < LCH; t++) {
        y = lam * y + c * xp[(size_t)t * DD];
        float ss = y * y;
        #pragma unroll
        for (int o = 16; o; o >>= 1) ss += __shfl_xor_sync(0xffffffffu, ss, o);
        if (lane == 0) red[wid] = ss;
        __syncthreads();
        if (wid == 0) {
            float v = red[lane];
            #pragma unroll
            for (int o = 16; o; o >>= 1) v += __shfl_xor_sync(0xffffffffu, v, o);
            if (lane == 0) red[0] = rsqrtf(v * (1.f / DD) + EPSF);
        }
        __syncthreads();
        float scale = red[0];
        __syncthreads();   // protect red[0] from next iteration's writes
        yp[(size_t)t * DD] = y * scale * w;
    }
}

// ---------------- K4: GEMM  out[M,1024] = Y[M,1024] @ W[1024,1024]^T ---------
// TN layout (both operands K-contiguous). 128x128x16 block tile, 256 threads,
// 8x8 register micro-tiles, double-buffered smem, float4 everywhere.
__global__ __launch_bounds__(256, 2)
void gemm_kernel(const float* __restrict__ A,   // [M][K]  M=BB*NN, K=DD
                 const float* __restrict__ Wt,  // [1024][K] (row i = output col i)
                 float* __restrict__ Cout) {    // [M][1024]
    const int K = DD;
    const int NO = DD;
    __shared__ float As[2][16][132];
    __shared__ float Bs[2][16][132];

    int tid = threadIdx.x;
    int bn = blockIdx.x;   // 0..7   (output-column tile)
    int bm = blockIdx.y;   // 0..127 (row tile)

    // global -> smem load mapping: 64 rows x 16 cols per pass, 2 passes
    int lr = tid >> 2;           // 0..63
    int lc = (tid & 3) << 2;     // 0,4,8,12

    const float* Ag = A  + (size_t)(bm * 128 + lr) * K + lc;
    const float* Wg = Wt + (size_t)(bn * 128 + lr) * K + lc;

    float4 a0 = *(const float4*)(Ag);
    float4 a1 = *(const float4*)(Ag + (size_t)64 * K);
    float4 w0 = *(const float4*)(Wg);
    float4 w1 = *(const float4*)(Wg + (size_t)64 * K);

    As[0][lc + 0][lr] = a0.x; As[0][lc + 1][lr] = a0.y;
    As[0][lc + 2][lr] = a0.z; As[0][lc + 3][lr] = a0.w;
    As[0][lc + 0][lr + 64] = a1.x; As[0][lc + 1][lr + 64] = a1.y;
    As[0][lc + 2][lr + 64] = a1.z; As[0][lc + 3][lr + 64] = a1.w;
    Bs[0][lc + 0][lr] = w0.x; Bs[0][lc + 1][lr] = w0.y;
    Bs[0][lc + 2][lr] = w0.z; Bs[0][lc + 3][lr] = w0.w;
    Bs[0][lc + 0][lr + 64] = w1.x; Bs[0][lc + 1][lr + 64] = w1.y;
    Bs[0][lc + 2][lr + 64] = w1.z; Bs[0][lc + 3][lr + 64] = w1.w;
    __syncthreads();

    int ty = tid >> 4, tx = tid & 15;
    int m0 = ty * 8, n0 = tx * 8;

    float acc[8][8];
    #pragma unroll
    for (int i = 0; i < 8; i++)
        #pragma unroll
        for (int j = 0; j < 8; j++) acc[i][j] = 0.f;

    const int nk = K / 16;   // 64
    for (int kt = 0; kt < nk; kt++) {
        int cur = kt & 1;
        if (kt + 1 < nk) {
            const float* Ag2 = Ag + (size_t)(kt + 1) * 16;
            const float* Wg2 = Wg + (size_t)(kt + 1) * 16;
            a0 = *(const float4*)(Ag2);
            a1 = *(const float4*)(Ag2 + (size_t)64 * K);
            w0 = *(const float4*)(Wg2);
            w1 = *(const float4*)(Wg2 + (size_t)64 * K);
        }
        #pragma unroll
        for (int k = 0; k < 16; k++) {
            float ar[8], br[8];
            *(float4*)&ar[0] = *(const float4*)&As[cur][k][m0];
            *(float4*)&ar[4] = *(const float4*)&As[cur][k][m0 + 4];
            *(float4*)&br[0] = *(const float4*)&Bs[cur][k][n0];
            *(float4*)&br[4] = *(const float4*)&Bs[cur][k][n0 + 4];
            #pragma unroll
            for (int i = 0; i < 8; i++)
                #pragma unroll
                for (int j = 0; j < 8; j++)
                    acc[i][j] += ar[i] * br[j];
        }
        if (kt + 1 < nk) {
            int nxt = cur ^ 1;
            As[nxt][lc + 0][lr] = a0.x; As[nxt][lc + 1][lr] = a0.y;
            As[nxt][lc + 2][lr] = a0.z; As[nxt][lc + 3][lr] = a0.w;
            As[nxt][lc + 0][lr + 64] = a1.x; As[nxt][lc + 1][lr + 64] = a1.y;
            As[nxt][lc + 2][lr + 64] = a1.z; As[nxt][lc + 3][lr + 64] = a1.w;
            Bs[nxt][lc + 0][lr] = w0.x; Bs[nxt][lc + 1][lr] = w0.y;
            Bs[nxt][lc + 2][lr] = w0.z; Bs[nxt][lc + 3][lr] = w0.w;
            Bs[nxt][lc + 0][lr + 64] = w1.x; Bs[nxt][lc + 1][lr + 64] = w1.y;
            Bs[nxt][lc + 2][lr + 64] = w1.z; Bs[nxt][lc + 3][lr + 64] = w1.w;
            __syncthreads();
        }
    }

    float* Cp = Cout + (size_t)(bm * 128 + m0) * NO + bn * 128 + n0;
    #pragma unroll
    for (int i = 0; i < 8; i++) {
        *(float4*)(Cp + (size_t)i * NO) =
            make_float4(acc[i][0], acc[i][1], acc[i][2], acc[i][3]);
        *(float4*)(Cp + (size_t)i * NO + 4) =
            make_float4(acc[i][4], acc[i][5], acc[i][6], acc[i][7]);
    }
}

// ---------------- launch -----------------------------------------------------
extern "C" void kernel_launch(void* const* d_in, const int* in_sizes, int n_in,
                              void* d_out, int out_size) {
    const float* x  = (const float*)d_in[0];   // (4,4096,1024)
    const float* q  = (const float*)d_in[1];   // (1024,)
    const float* k  = (const float*)d_in[2];   // (1024,)
    const float* ld = (const float*)d_in[3];   // (16,)
    const float* nw = (const float*)d_in[4];   // (1024,)
    const float* ow = (const float*)d_in[5];   // (1024,1024)
    float* out = (float*)d_out;

    setup_kernel<<<1, 32>>>(q, k, ld);
    scan_carry_kernel<<<dim3(NCH, BB), DD>>>(x);
    scan_combine_kernel<<<BB, DD>>>();
    scan_norm_kernel<<<dim3(NCH, BB), DD>>>(x, nw);

    float* ynorm;
    cudaGetSymbolAddress((void**)&ynorm, g_ynorm);
    gemm_kernel<<<dim3(DD / 128, (BB * NN) / 128), 256>>>(ynorm, ow, out);
}

// round 10
// speedup vs baseline: 2.6524x; 2.6524x over previous
#include <cuda_runtime.h>
#include <cuda_fp16.h>
#include <cstdint>

// Problem constants (fixed by reference setup_inputs)
#define BB 4
#define NN 4096
#define DD 1024
#define HH 16
#define DH 64
#define NCH 32          // chunks along sequence
#define LCH 128         // steps per chunk
#define EPSF 1e-6f
#define MTOT (BB * NN)  // 16384 rows

// ---------------- scratch (__device__ globals: allocation-free) -------------
__device__ float g_lam[HH];
__device__ float g_c[HH];
__device__ float g_lamL[HH];
__device__ float g_carry[BB * NCH * DD];
__device__ float g_inflow[BB * NCH * DD];
__device__ float g_rscale[MTOT];
__device__ __align__(256) __half g_yhi[(size_t)MTOT * DD];  // 32 MB
__device__ __align__(256) __half g_ylo[(size_t)MTOT * DD];  // 32 MB
__device__ __align__(256) __half g_whi[DD * DD];
__device__ __align__(256) __half g_wlo[DD * DD];

// ---------------- small PTX helpers (baseline sm_80+ features only) ----------
__device__ __forceinline__ uint32_t smem_u32(const void* p) {
    uint32_t a;
    asm("{ .reg .u64 t; cvta.to.shared.u64 t, %1; cvt.u32.u64 %0, t; }"
        : "=r"(a) : "l"(p));
    return a;
}
__device__ __forceinline__ void cp16(uint32_t dst, const void* src) {
    asm volatile("cp.async.cg.shared.global [%0], [%1], 16;"
                 :: "r"(dst), "l"(src) : "memory");
}
__device__ __forceinline__ void cp_commit() {
    asm volatile("cp.async.commit_group;" ::: "memory");
}
template <int N>
__device__ __forceinline__ void cp_wait() {
    asm volatile("cp.async.wait_group %0;" :: "n"(N) : "memory");
}
__device__ __forceinline__ void ldsm_x4(uint32_t* r, uint32_t addr) {
    asm volatile("ldmatrix.sync.aligned.m8n8.x4.shared.b16 {%0,%1,%2,%3}, [%4];"
                 : "=r"(r[0]), "=r"(r[1]), "=r"(r[2]), "=r"(r[3]) : "r"(addr));
}
__device__ __forceinline__ void mma16816(float* c, const uint32_t* a,
                                         uint32_t b0, uint32_t b1) {
    asm volatile(
        "mma.sync.aligned.m16n8k16.row.col.f32.f16.f16.f32 "
        "{%0,%1,%2,%3},{%4,%5,%6,%7},{%8,%9},{%0,%1,%2,%3};"
        : "+f"(c[0]), "+f"(c[1]), "+f"(c[2]), "+f"(c[3])
        : "r"(a[0]), "r"(a[1]), "r"(a[2]), "r"(a[3]), "r"(b0), "r"(b1));
}

// ---------------- K0: per-head constants ------------------------------------
__global__ void setup_kernel(const float* __restrict__ q,
                             const float* __restrict__ k,
                             const float* __restrict__ ld) {
    int h = threadIdx.x;
    if (h < HH) {
        float lam = 1.f / (1.f + expf(-ld[h]));
        float c = 0.f;
        #pragma unroll
        for (int i = 0; i < DH; i++) c += q[h * DH + i] * k[h * DH + i];
        float p = lam;
        #pragma unroll
        for (int it = 0; it < 7; it++) p = p * p;    // lam^128
        g_lam[h] = lam; g_c[h] = c; g_lamL[h] = p;
    }
}

// ---------------- K1: weights: fold nw, split fp16 hi/lo ---------------------
__global__ void wconv_kernel(const float* __restrict__ ow,
                             const float* __restrict__ nw) {
    int n = blockIdx.x;
    for (int k = threadIdx.x; k < DD; k += blockDim.x) {
        float w = ow[n * DD + k] * nw[k];
        __half hi = __float2half_rn(w);
        g_whi[n * DD + k] = hi;
        g_wlo[n * DD + k] = __float2half_rn(w - __half2float(hi));
    }
}

// ---------------- K2: per-chunk carries --------------------------------------
__global__ void scan_carry_kernel(const float* __restrict__ x) {
    int d = threadIdx.x, ch = blockIdx.x, b = blockIdx.y;
    int h = d >> 6;
    float lam = g_lam[h], c = g_c[h];
    const float* xp = x + ((size_t)(b * NN) + ch * LCH) * DD + d;
    float y = 0.f;
    #pragma unroll 8
    for (int t = 0; t < LCH; t++) y = lam * y + c * xp[(size_t)t * DD];
    g_carry[(b * NCH + ch) * DD + d] = y;
}

// ---------------- K3: serial combine across chunks ---------------------------
__global__ void scan_combine_kernel() {
    int d = threadIdx.x, b = blockIdx.x;
    int h = d >> 6;
    float lamL = g_lamL[h];
    float s = 0.f;
    int base = b * NCH * DD + d;
    #pragma unroll
    for (int ch = 0; ch < NCH; ch++) {
        g_inflow[base + ch * DD] = s;
        s = lamL * s + g_carry[base + ch * DD];
    }
}

// ---------------- K4: final scan, store y as fp16 hi/lo (no barriers) --------
__global__ void scan_store_kernel(const float* __restrict__ x) {
    int d = threadIdx.x, ch = blockIdx.x, b = blockIdx.y;
    int h = d >> 6;
    float lam = g_lam[h], c = g_c[h];
    float y = g_inflow[(b * NCH + ch) * DD + d];
    size_t base = ((size_t)(b * NN) + ch * LCH) * DD + d;
    const float* xp = x + base;
    __half* hp = g_yhi + base;
    __half* lp = g_ylo + base;
    #pragma unroll 4
    for (int t = 0; t < LCH; t++) {
        y = lam * y + c * xp[(size_t)t * DD];
        __half hi = __float2half_rn(y);
        hp[(size_t)t * DD] = hi;
        lp[(size_t)t * DD] = __float2half_rn(y - __half2float(hi));
    }
}

// ---------------- K5: per-row rsqrt(mean(y^2)+eps) ---------------------------
// grid 512, block 1024: one warp per row.
__global__ void rowscale_kernel() {
    int wid = threadIdx.x >> 5, lane = threadIdx.x & 31;
    int row = blockIdx.x * 32 + wid;
    const uint4* hp = (const uint4*)(g_yhi + (size_t)row * DD);
    const uint4* lp = (const uint4*)(g_ylo + (size_t)row * DD);
    float ss = 0.f;
    #pragma unroll
    for (int i = 0; i < 4; i++) {
        uint4 hv = hp[lane + i * 32];
        uint4 lv = lp[lane + i * 32];
        const __half* hb = (const __half*)&hv;
        const __half* lb = (const __half*)&lv;
        #pragma unroll
        for (int j = 0; j < 8; j++) {
            float v = __half2float(hb[j]) + __half2float(lb[j]);
            ss += v * v;
        }
    }
    #pragma unroll
    for (int o = 16; o; o >>= 1) ss += __shfl_xor_sync(0xffffffffu, ss, o);
    if (lane == 0) g_rscale[row] = rsqrtf(ss * (1.f / DD) + EPSF);
}

// ---------------- K6: HMMA GEMM  out = rscale[m] * (Y @ Wc^T) ----------------
// 128x128 CTA tile, K-chunk 32 halves, 8 warps (64x32 each), double-buffered
// cp.async. 3-pass split precision AhBh + AlBh + AhBl from ONE smem stage.
// SMEM stage layout: Ah(8K) Al(8K) Bh(8K) Bl(8K) = 32KB. XOR swizzle:
// element (row r, 16B-chunk c) at r*64 + ((c ^ ((r>>1)&3))*16) -> conflict-free
// ldmatrix phases and cp.async stores.
#define STAGE_B 32768
#define TILE_B 8192

__global__ __launch_bounds__(256, 2)
void gemm_kernel(float* __restrict__ out) {
    extern __shared__ char smem[];
    uint32_t sb = smem_u32(smem);
    int tid = threadIdx.x, lane = tid & 31, wid = tid >> 5;
    int bn = blockIdx.x;     // 0..7
    int bm = blockIdx.y;     // 0..127
    int wm = wid & 1;        // 0..1  -> 64-row half
    int wn = wid >> 1;       // 0..3  -> 32-col quarter

    const __half* gAh = g_yhi + (size_t)(bm * 128) * DD;
    const __half* gAl = g_ylo + (size_t)(bm * 128) * DD;
    const __half* gBh = g_whi + (size_t)(bn * 128) * DD;
    const __half* gBl = g_wlo + (size_t)(bn * 128) * DD;

    // loader mapping: each thread owns 2 (row, chunk) slots per tile
    int lr0 = tid >> 2, lc0 = tid & 3;                 // slot 0
    int lr1 = (tid + 256) >> 2, lc1 = lc0;             // slot 1 (rows 64..127)
    uint32_t d_off0 = (uint32_t)(lr0 * 64 + ((lc0 ^ ((lr0 >> 1) & 3)) << 4));
    uint32_t d_off1 = (uint32_t)(lr1 * 64 + ((lc1 ^ ((lr1 >> 1) & 3)) << 4));
    size_t s_off0 = (size_t)lr0 * DD + lc0 * 8;
    size_t s_off1 = (size_t)lr1 * DD + lc1 * 8;

    auto stage_load = [&](uint32_t stb, int c) {
        int kof = c * 32;
        const __half* s[4] = { gAh, gAl, gBh, gBl };
        #pragma unroll
        for (int t = 0; t < 4; t++) {
            cp16(stb + t * TILE_B + d_off0, s[t] + s_off0 + kof);
            cp16(stb + t * TILE_B + d_off1, s[t] + s_off1 + kof);
        }
        cp_commit();
    };

    // ldmatrix per-lane address components
    int am = lane >> 3, alr = lane & 7;
    uint32_t a_row = (uint32_t)(wm * 64 + (am & 1) * 8 + alr);
    uint32_t a_base = a_row * 64;                 // + mt*1024
    uint32_t a_sw = (alr >> 1) & 3;
    uint32_t a_ck0 = (uint32_t)(am >> 1);         // + kt*2
    uint32_t b_row = (uint32_t)(wn * 32 + ((am >> 1) & 1) * 8 + alr);
    uint32_t b_base = b_row * 64;                 // + p*1024
    uint32_t b_sw = (alr >> 1) & 3;
    uint32_t b_ck0 = (uint32_t)(am & 1);          // + kt*2

    float acc[4][4][4];
    #pragma unroll
    for (int i = 0; i < 4; i++)
        #pragma unroll
        for (int j = 0; j < 4; j++)
            #pragma unroll
            for (int v = 0; v < 4; v++) acc[i][j][v] = 0.f;

    stage_load(sb, 0);
    stage_load(sb + STAGE_B, 1);

    for (int c = 0; c < 32; c++) {
        uint32_t stb = sb + (uint32_t)(c & 1) * STAGE_B;
        if (c < 31) cp_wait<1>(); else cp_wait<0>();
        __syncthreads();

        uint32_t Ah = stb, Al = stb + TILE_B, Bh = stb + 2 * TILE_B, Bl = stb + 3 * TILE_B;
        #pragma unroll
        for (int kt = 0; kt < 2; kt++) {
            uint32_t a_ck = (((uint32_t)(kt * 2) + a_ck0) ^ a_sw) << 4;
            uint32_t b_ck = (((uint32_t)(kt * 2) + b_ck0) ^ b_sw) << 4;
            uint32_t ah[4][4], al[4][4], bh[4][2], bl[4][2];
            #pragma unroll
            for (int mt = 0; mt < 4; mt++)
                ldsm_x4(ah[mt], Ah + a_base + mt * 1024 + a_ck);
            {   // Bh frags: two x4 loads -> 4 n-tiles
                uint32_t r[4];
                ldsm_x4(r, Bh + b_base + b_ck);
                bh[0][0] = r[0]; bh[0][1] = r[1]; bh[1][0] = r[2]; bh[1][1] = r[3];
                ldsm_x4(r, Bh + b_base + 1024 + b_ck);
                bh[2][0] = r[0]; bh[2][1] = r[1]; bh[3][0] = r[2]; bh[3][1] = r[3];
            }
            #pragma unroll
            for (int mt = 0; mt < 4; mt++)
                #pragma unroll
                for (int nt = 0; nt < 4; nt++)
                    mma16816(acc[mt][nt], ah[mt], bh[nt][0], bh[nt][1]);
            #pragma unroll
            for (int mt = 0; mt < 4; mt++)
                ldsm_x4(al[mt], Al + a_base + mt * 1024 + a_ck);
            #pragma unroll
            for (int mt = 0; mt < 4; mt++)
                #pragma unroll
                for (int nt = 0; nt < 4; nt++)
                    mma16816(acc[mt][nt], al[mt], bh[nt][0], bh[nt][1]);
            {   // Bl frags
                uint32_t r[4];
                ldsm_x4(r, Bl + b_base + b_ck);
                bl[0][0] = r[0]; bl[0][1] = r[1]; bl[1][0] = r[2]; bl[1][1] = r[3];
                ldsm_x4(r, Bl + b_base + 1024 + b_ck);
                bl[2][0] = r[0]; bl[2][1] = r[1]; bl[3][0] = r[2]; bl[3][1] = r[3];
            }
            #pragma unroll
            for (int mt = 0; mt < 4; mt++)
                #pragma unroll
                for (int nt = 0; nt < 4; nt++)
                    mma16816(acc[mt][nt], ah[mt], bl[nt][0], bl[nt][1]);
        }
        __syncthreads();
        if (c + 2 < 32) stage_load(stb, c + 2);
    }

    // epilogue: apply per-row rscale, write fp32
    int r0 = bm * 128 + wm * 64 + (lane >> 2);
    int cb = bn * 128 + wn * 32 + (lane & 3) * 2;
    #pragma unroll
    for (int mt = 0; mt < 4; mt++) {
        int r = r0 + mt * 16;
        float s0 = g_rscale[r];
        float s1 = g_rscale[r + 8];
        #pragma unroll
        for (int nt = 0; nt < 4; nt++) {
            float2 v0 = make_float2(acc[mt][nt][0] * s0, acc[mt][nt][1] * s0);
            float2 v1 = make_float2(acc[mt][nt][2] * s1, acc[mt][nt][3] * s1);
            *(float2*)(out + (size_t)r * DD + cb + nt * 8) = v0;
            *(float2*)(out + (size_t)(r + 8) * DD + cb + nt * 8) = v1;
        }
    }
}

// ---------------- launch -----------------------------------------------------
extern "C" void kernel_launch(void* const* d_in, const int* in_sizes, int n_in,
                              void* d_out, int out_size) {
    const float* x  = (const float*)d_in[0];   // (4,4096,1024)
    const float* q  = (const float*)d_in[1];   // (1024,)
    const float* k  = (const float*)d_in[2];   // (1024,)
    const float* ld = (const float*)d_in[3];   // (16,)
    const float* nw = (const float*)d_in[4];   // (1024,)
    const float* ow = (const float*)d_in[5];   // (1024,1024)
    float* out = (float*)d_out;

    cudaFuncSetAttribute(gemm_kernel,
                         cudaFuncAttributeMaxDynamicSharedMemorySize, 2 * STAGE_B);

    setup_kernel<<<1, 32>>>(q, k, ld);
    wconv_kernel<<<DD, 256>>>(ow, nw);
    scan_carry_kernel<<<dim3(NCH, BB), DD>>>(x);
    scan_combine_kernel<<<BB, DD>>>();
    scan_store_kernel<<<dim3(NCH, BB), DD>>>(x);
    rowscale_kernel<<<MTOT / 32, 1024>>>();
    gemm_kernel<<<dim3(DD / 128, MTOT / 128), 256, 2 * STAGE_B>>>(out);
}